// round 1
// baseline (speedup 1.0000x reference)
#include <cuda_runtime.h>
#include <math.h>

#define B_ROWS 65536
#define DIM    512
#define BD     (B_ROWS * DIM)
#define EPSF   1e-15f
#define MAXN   0.996f          /* 1 - 4e-3 */
#define CLIPA  (1.0f - 1e-7f)

// ------------------------------------------------------------------
// Scratch (static device memory; allocation-free kernel_launch)
// ------------------------------------------------------------------
__device__ float g_u[BD];        // expmap0(logmap(xp,xc))  [B, D]
__device__ float g_inner[BD];    // u @ z (raw, pre /zn)    [B, D]
__device__ float g_cu2[B_ROWS];  // ||u||^2 per row
__device__ float g_x2c[B_ROWS];  // ||x_current||^2 per row
__device__ float g_zn[DIM];      // column norms of z
__device__ float g_ch[DIM];      // cosh(2*bias)
__device__ float g_sh[DIM];      // sinh(2*bias)

// ------------------------------------------------------------------
// Block reduction over 128 threads (4 warps)
// ------------------------------------------------------------------
__device__ __forceinline__ float block_reduce(float v, volatile float* sb) {
    int lane = threadIdx.x & 31;
    int w    = threadIdx.x >> 5;
#pragma unroll
    for (int o = 16; o; o >>= 1) v += __shfl_down_sync(0xffffffffu, v, o);
    __syncthreads();              // protect sb from previous use
    if (lane == 0) sb[w] = v;
    __syncthreads();
    return sb[0] + sb[1] + sb[2] + sb[3];
}

// ------------------------------------------------------------------
// Kernel 1: per-column z stats: zn = sqrt(max(sum_i z[i][j]^2, EPS)),
//           ch/sh of 2*bias
// ------------------------------------------------------------------
__global__ void prep_cols(const float* __restrict__ z,
                          const float* __restrict__ bias) {
    __shared__ float sb[4];
    int j = blockIdx.x;           // 0..511
    float s = 0.f;
    for (int i = threadIdx.x; i < DIM; i += 128) {
        float v = z[i * DIM + j];
        s += v * v;
    }
    s = block_reduce(s, sb);
    if (threadIdx.x == 0) {
        g_zn[j] = sqrtf(fmaxf(s, EPSF));
        float tb = 2.f * bias[j];
        g_ch[j] = coshf(tb);
        g_sh[j] = sinhf(tb);
    }
}

// ------------------------------------------------------------------
// Kernel 2: per row, bt = logmap(xp, xc); u = expmap0(bt); store u,
//           ||u||^2, ||xc||^2.
// 128 threads/row, float4 per thread.
// ------------------------------------------------------------------
__global__ void prep_rows(const float* __restrict__ xc_g,
                          const float* __restrict__ xp_g) {
    __shared__ float sb[4];
    int b = blockIdx.x;
    int t = threadIdx.x;
    float4 xc = ((const float4*)(xc_g + (size_t)b * DIM))[t];
    float4 xp = ((const float4*)(xp_g + (size_t)b * DIM))[t];

    float px2 = xp.x*xp.x + xp.y*xp.y + xp.z*xp.z + xp.w*xp.w;
    float py2 = xc.x*xc.x + xc.y*xc.y + xc.z*xc.z + xc.w*xc.w;
    float pxy = xp.x*xc.x + xp.y*xc.y + xp.z*xc.z + xp.w*xc.w;

    float x2p = block_reduce(px2, sb);
    float y2  = block_reduce(py2, sb);
    float xy  = block_reduce(pxy, sb);

    // mobius_add(-xp, xc): num = fA*(-xp) + fB*xc ; den = 1 - 2xy + x2p*y2
    float fA = 1.f - 2.f * xy + y2;
    float fB = 1.f - x2p;
    float inv_den = 1.f / fmaxf(1.f - 2.f * xy + x2p * y2, EPSF);

    float4 sub;
    sub.x = (fB * xc.x - fA * xp.x) * inv_den;
    sub.y = (fB * xc.y - fA * xp.y) * inv_den;
    sub.z = (fB * xc.z - fA * xp.z) * inv_den;
    sub.w = (fB * xc.w - fA * xp.w) * inv_den;

    float psn2 = sub.x*sub.x + sub.y*sub.y + sub.z*sub.z + sub.w*sub.w;
    float sn2  = block_reduce(psn2, sb);
    float sn   = sqrtf(fmaxf(sn2, EPSF));

    // bt = max(1-x2p,EPS) * artanh(sn)/sn * sub ; u = tanh(|bt|)*bt/|bt|
    float c  = fmaxf(fB, EPSF) * atanhf(fminf(sn, CLIPA)) / sn;
    float un = sqrtf(fmaxf(c * c * sn2, EPSF));
    float s  = tanhf(un) * c / un;

    float4 u;
    u.x = s * sub.x; u.y = s * sub.y; u.z = s * sub.z; u.w = s * sub.w;
    ((float4*)(g_u + (size_t)b * DIM))[t] = u;

    if (t == 0) {
        g_cu2[b] = s * s * sn2;   // ||u||^2
        g_x2c[b] = y2;            // ||x_current||^2
    }
}

// ------------------------------------------------------------------
// Kernel 3: SGEMM g_inner = g_u @ z   (65536x512 @ 512x512, fp32)
// 64x64 tile, BK=16, 256 threads, 4x4 per thread, float4 smem.
// ------------------------------------------------------------------
__global__ void __launch_bounds__(256)
sgemm(const float* __restrict__ Bz) {
    __shared__ __align__(16) float As[16][64];
    __shared__ __align__(16) float Bs[16][64];

    int tid = threadIdx.x;
    int tx  = tid & 15;          // 0..15
    int ty  = tid >> 4;          // 0..15
    int m0  = blockIdx.y * 64;
    int n0  = blockIdx.x * 64;

    float acc[4][4] = {};

    int arow = tid >> 2;                // 0..63
    int acol = (tid & 3) * 4;           // 0,4,8,12
    int brow = tid >> 4;                // 0..15
    int bcol = (tid & 15) * 4;          // 0..60

    const float* Aptr = g_u + (size_t)(m0 + arow) * DIM + acol;
    const float* Bptr = Bz + (size_t)brow * DIM + n0 + bcol;

    for (int k0 = 0; k0 < DIM; k0 += 16) {
        float4 a4 = *(const float4*)(Aptr + k0);
        float4 b4 = *(const float4*)(Bptr + (size_t)k0 * DIM);
        As[acol + 0][arow] = a4.x;
        As[acol + 1][arow] = a4.y;
        As[acol + 2][arow] = a4.z;
        As[acol + 3][arow] = a4.w;
        *(float4*)&Bs[brow][bcol] = b4;
        __syncthreads();
#pragma unroll
        for (int kk = 0; kk < 16; kk++) {
            float4 av = *(const float4*)&As[kk][ty * 4];
            float4 bv = *(const float4*)&Bs[kk][tx * 4];
            acc[0][0] += av.x * bv.x; acc[0][1] += av.x * bv.y;
            acc[0][2] += av.x * bv.z; acc[0][3] += av.x * bv.w;
            acc[1][0] += av.y * bv.x; acc[1][1] += av.y * bv.y;
            acc[1][2] += av.y * bv.z; acc[1][3] += av.y * bv.w;
            acc[2][0] += av.z * bv.x; acc[2][1] += av.z * bv.y;
            acc[2][2] += av.z * bv.z; acc[2][3] += av.z * bv.w;
            acc[3][0] += av.w * bv.x; acc[3][1] += av.w * bv.y;
            acc[3][2] += av.w * bv.z; acc[3][3] += av.w * bv.w;
        }
        __syncthreads();
    }

    int crow = m0 + ty * 4;
    int ccol = n0 + tx * 4;
#pragma unroll
    for (int i = 0; i < 4; i++) {
        float4 v = make_float4(acc[i][0], acc[i][1], acc[i][2], acc[i][3]);
        *(float4*)&g_inner[(size_t)(crow + i) * DIM + ccol] = v;
    }
}

// ------------------------------------------------------------------
// Kernel 4: per row — poincare_fc epilogue, logmap0, expmap,
// residual mobius update, final projections. All tail norms are
// analytic in {x2, w2s, xw}, so only 2 reductions are needed.
// ------------------------------------------------------------------
__global__ void finish_rows(const float* __restrict__ xc_g,
                            const float* __restrict__ alpha_p,
                            const float* __restrict__ step_p,
                            float* __restrict__ out) {
    __shared__ float sb[4];
    int b = blockIdx.x;
    int t = threadIdx.x;

    float4 in4 = ((const float4*)(g_inner + (size_t)b * DIM))[t];
    float4 zn4 = ((const float4*)g_zn)[t];
    float4 ch4 = ((const float4*)g_ch)[t];
    float4 sh4 = ((const float4*)g_sh)[t];
    float4 xc  = ((const float4*)(xc_g + (size_t)b * DIM))[t];

    float cu2   = g_cu2[b];
    float x2    = g_x2c[b];
    float invdn = 1.f / fmaxf(1.f - cu2, EPSF);
    float op    = 1.f + cu2;

    // w = sinh(2*zn*asinh((2*inner*cosh - (1+cx2)*sinh)/denom)), inner = raw/zn
    float4 w;
    w.x = sinhf(2.f * zn4.x * asinhf((2.f * (in4.x / zn4.x) * ch4.x - op * sh4.x) * invdn));
    w.y = sinhf(2.f * zn4.y * asinhf((2.f * (in4.y / zn4.y) * ch4.y - op * sh4.y) * invdn));
    w.z = sinhf(2.f * zn4.z * asinhf((2.f * (in4.z / zn4.z) * ch4.z - op * sh4.z) * invdn));
    w.w = sinhf(2.f * zn4.w * asinhf((2.f * (in4.w / zn4.w) * ch4.w - op * sh4.w) * invdn));

    float pw2 = w.x*w.x + w.y*w.y + w.z*w.z + w.w*w.w;
    float pxw = xc.x*w.x + xc.y*w.y + xc.z*w.z + xc.w*w.w;
    float w2s = block_reduce(pw2, sb);
    float xw  = block_reduce(pxw, sb);

    // y = w/g ; vel = logmap0(y) = (atanh(yn)/yn) * y
    float g   = 1.f + sqrtf(1.f + w2s);
    float y2s = w2s / (g * g);
    float yn  = sqrtf(fmaxf(y2s, EPSF));
    float kv  = atanhf(fminf(yn, CLIPA)) / yn;

    float step = 1.f / (1.f + expf(-step_p[0]));
    float m0   = step * kv / g;                 // u' = m0 * w
    float un   = sqrtf(fmaxf(m0 * m0 * w2s, EPSF));
    float lam  = 2.f / fmaxf(1.f - x2, EPSF);
    float mt   = tanhf(0.5f * lam * un) * m0 / un;   // t = mt * w

    // mobius_add(xc, t)
    float t2   = mt * mt * w2s;
    float xt   = mt * xw;
    float p    = 1.f + 2.f * xt + t2;
    float q    = 1.f - x2;
    float den2 = fmaxf(1.f + 2.f * xt + x2 * t2, EPSF);
    float a1   = p / den2;                      // xu = a1*xc + b1*w
    float b1   = q * mt / den2;

    // projx(xu)
    float nxu2 = a1 * a1 * x2 + 2.f * a1 * b1 * xw + b1 * b1 * w2s;
    float nxu  = sqrtf(fmaxf(nxu2, EPSF));
    float fxu  = (nxu > MAXN) ? MAXN / nxu : 1.f;
    a1 *= fxu; b1 *= fxu;
    float nxup = fminf(nxu, MAXN);

    // projx(xc)  -> second output
    float nxc  = sqrtf(fmaxf(x2, EPSF));
    float fxc  = (nxc > MAXN) ? MAXN / nxc : 1.f;
    float nxcp = fminf(nxc, MAXN);

    float aa = 1.f / (1.f + expf(-alpha_p[0]));

    // mobius_scalar_mul(aa, xcp):   m1 = A1 * xc,  ||m1|| = th1
    float th1 = tanhf(aa * atanhf(fminf(nxcp, CLIPA)));
    float A1  = th1 / nxcp * fxc;
    // mobius_scalar_mul(1-aa, xup): m2 = A2*xc + B2*w, ||m2|| = th2
    float th2 = tanhf((1.f - aa) * atanhf(fminf(nxup, CLIPA)));
    float r2  = th2 / nxup;
    float A2  = r2 * a1;
    float B2  = r2 * b1;

    // mobius_add(m1, m2)
    float x2m = th1 * th1;
    float y2m = th2 * th2;
    float xym = A1 * (A2 * x2 + B2 * xw);
    float P   = 1.f + 2.f * xym + y2m;
    float Q   = 1.f - x2m;
    float den3 = fmaxf(1.f + 2.f * xym + x2m * y2m, EPSF);
    float CA  = (P * A1 + Q * A2) / den3;       // x_next = CA*xc + CB*w
    float CB  = (Q * B2) / den3;

    // final projx
    float nn2 = CA * CA * x2 + 2.f * CA * CB * xw + CB * CB * w2s;
    float nn  = sqrtf(fmaxf(nn2, EPSF));
    float fo  = (nn > MAXN) ? MAXN / nn : 1.f;
    CA *= fo; CB *= fo;

    float4 o1, o2;
    o1.x = CA * xc.x + CB * w.x;  o2.x = fxc * xc.x;
    o1.y = CA * xc.y + CB * w.y;  o2.y = fxc * xc.y;
    o1.z = CA * xc.z + CB * w.z;  o2.z = fxc * xc.z;
    o1.w = CA * xc.w + CB * w.w;  o2.w = fxc * xc.w;

    ((float4*)out)[(size_t)b * 128 + t]             = o1;   // x_next
    ((float4*)(out + (size_t)BD))[(size_t)b * 128 + t] = o2; // xc (projected)
}

// ------------------------------------------------------------------
extern "C" void kernel_launch(void* const* d_in, const int* in_sizes, int n_in,
                              void* d_out, int out_size) {
    const float* xc    = (const float*)d_in[0];
    const float* xp    = (const float*)d_in[1];
    const float* z     = (const float*)d_in[2];
    const float* bias  = (const float*)d_in[3];
    const float* alpha = (const float*)d_in[4];
    const float* stepz = (const float*)d_in[5];
    float* out = (float*)d_out;

    prep_cols<<<DIM, 128>>>(z, bias);
    prep_rows<<<B_ROWS, 128>>>(xc, xp);
    sgemm<<<dim3(DIM / 64, B_ROWS / 64), 256>>>(z);
    finish_rows<<<B_ROWS, 128>>>(xc, alpha, stepz, out);
}

// round 3
// speedup vs baseline: 2.7150x; 2.7150x over previous
#include <cuda_runtime.h>
#include <cuda_bf16.h>
#include <stdint.h>
#include <math.h>

#define B_ROWS 65536
#define DIM    512
#define KTOT   1536            /* [Uh | Ul | Uh] x [Zh | Zh | Zl] */
#define BD     (B_ROWS * DIM)
#define EPSF   1e-15f
#define MAXN   0.996f
#define CLIPA  (1.0f - 1e-7f)

// ------------------------------------------------------------------
// Static scratch
// ------------------------------------------------------------------
__device__ __align__(16) __nv_bfloat16 g_ub[(size_t)B_ROWS * KTOT]; // A' [B][1536]
__device__ __align__(16) __nv_bfloat16 g_zb[DIM * KTOT];            // B' [out j][1536]
__device__ __align__(16) float g_inner[BD];
__device__ float g_cu2[B_ROWS];
__device__ float g_x2c[B_ROWS];
__device__ __align__(16) float g_c1[DIM];   // 2*cosh(2b)/zn
__device__ __align__(16) float g_c2[DIM];   // sinh(2b)
__device__ __align__(16) float g_s2[DIM];   // 2*zn

// ------------------------------------------------------------------
// Fast math (MUFU-based)
// ------------------------------------------------------------------
__device__ __forceinline__ float f_rcp(float x){ float y; asm("rcp.approx.f32 %0,%1;" : "=f"(y) : "f"(x)); return y; }
__device__ __forceinline__ float f_lg2(float x){ float y; asm("lg2.approx.f32 %0,%1;" : "=f"(y) : "f"(x)); return y; }
__device__ __forceinline__ float f_ex2(float x){ float y; asm("ex2.approx.f32 %0,%1;" : "=f"(y) : "f"(x)); return y; }
__device__ __forceinline__ float f_sqrt(float x){ float y; asm("sqrt.approx.f32 %0,%1;" : "=f"(y) : "f"(x)); return y; }

__device__ __forceinline__ float atanh_f(float x){          // x in [0,1)
    return 0.34657359028f * f_lg2((1.f + x) * f_rcp(1.f - x));
}
__device__ __forceinline__ float tanh_f(float x){           // x >= 0
    return 1.f - 2.f * f_rcp(f_ex2(x * 2.88539008178f) + 1.f);
}
__device__ __forceinline__ float sigmoid_f(float x){
    return f_rcp(1.f + f_ex2(-1.44269504089f * x));
}
// w = sinh(s * asinh(t))
__device__ __forceinline__ float sinh_asinh(float t, float s){
    float a = fabsf(t);
    float q = a + f_sqrt(fmaf(a, a, 1.f));
    float p = f_ex2(s * f_lg2(q));
    return copysignf(0.5f * (p - f_rcp(p)), t);
}

// ------------------------------------------------------------------
// Portable tensor-core primitives (sm_80 feature set — no 'a' gating)
// ------------------------------------------------------------------
__device__ __forceinline__ uint32_t s2u(const void* p){ return (uint32_t)__cvta_generic_to_shared(p); }

__device__ __forceinline__ void cp16(uint32_t dst, const void* src){
    asm volatile("cp.async.cg.shared.global [%0], [%1], 16;" :: "r"(dst), "l"(src));
}
__device__ __forceinline__ void cp_commit(){ asm volatile("cp.async.commit_group;" ::: "memory"); }
template<int N> __device__ __forceinline__ void cp_wait(){ asm volatile("cp.async.wait_group %0;" :: "n"(N) : "memory"); }

__device__ __forceinline__ void ldsm4(uint32_t* r, uint32_t addr){
    asm volatile("ldmatrix.sync.aligned.m8n8.x4.shared.b16 {%0,%1,%2,%3}, [%4];"
        : "=r"(r[0]),"=r"(r[1]),"=r"(r[2]),"=r"(r[3]) : "r"(addr));
}
__device__ __forceinline__ void mma16816(float* c, const uint32_t* a, uint32_t b0, uint32_t b1){
    asm volatile("mma.sync.aligned.m16n8k16.row.col.f32.bf16.bf16.f32 "
        "{%0,%1,%2,%3}, {%4,%5,%6,%7}, {%8,%9}, {%0,%1,%2,%3};"
        : "+f"(c[0]),"+f"(c[1]),"+f"(c[2]),"+f"(c[3])
        : "r"(a[0]),"r"(a[1]),"r"(a[2]),"r"(a[3]), "r"(b0),"r"(b1));
}

// ------------------------------------------------------------------
// Kernel 1: z stats + transposed bf16 split of z into B' = [Zh|Zh|Zl]
// ------------------------------------------------------------------
__global__ void prep_cols(const float* __restrict__ z, const float* __restrict__ bias){
    __shared__ float sb[4];
    int j = blockIdx.x, t = threadIdx.x;
    float s = 0.f;
    for (int i = t; i < DIM; i += 128){
        float v = z[i * DIM + j];
        s += v * v;
        __nv_bfloat16 h = __float2bfloat16(v);
        __nv_bfloat16 lo = __float2bfloat16(v - __bfloat162float(h));
        g_zb[j * KTOT + i]            = h;
        g_zb[j * KTOT + DIM + i]      = h;
        g_zb[j * KTOT + 2 * DIM + i]  = lo;
    }
#pragma unroll
    for (int o = 16; o; o >>= 1) s += __shfl_down_sync(0xffffffffu, s, o);
    if ((t & 31) == 0) sb[t >> 5] = s;
    __syncthreads();
    if (t == 0){
        float tot = sb[0] + sb[1] + sb[2] + sb[3];
        float zn = sqrtf(fmaxf(tot, EPSF));
        float tb = 2.f * bias[j];
        g_c1[j] = 2.f * coshf(tb) / zn;
        g_c2[j] = sinhf(tb);
        g_s2[j] = 2.f * zn;
    }
}

// ------------------------------------------------------------------
// Kernel 2: warp-per-row: u = expmap0(logmap(xp,xc)) -> A' = [Uh|Ul|Uh]
// ------------------------------------------------------------------
__global__ void __launch_bounds__(256) prep_rows(const float* __restrict__ xc_g,
                                                 const float* __restrict__ xp_g){
    int row = blockIdx.x * 8 + (threadIdx.x >> 5);
    int l   = threadIdx.x & 31;
    const float4* xc4 = (const float4*)(xc_g + (size_t)row * DIM);
    const float4* xp4 = (const float4*)(xp_g + (size_t)row * DIM);

    float4 xc[4], xp[4];
    float px2 = 0.f, py2 = 0.f, pxy = 0.f;
#pragma unroll
    for (int i = 0; i < 4; i++){
        xc[i] = xc4[i * 32 + l];
        xp[i] = xp4[i * 32 + l];
        px2 += xp[i].x*xp[i].x + xp[i].y*xp[i].y + xp[i].z*xp[i].z + xp[i].w*xp[i].w;
        py2 += xc[i].x*xc[i].x + xc[i].y*xc[i].y + xc[i].z*xc[i].z + xc[i].w*xc[i].w;
        pxy += xp[i].x*xc[i].x + xp[i].y*xc[i].y + xp[i].z*xc[i].z + xp[i].w*xc[i].w;
    }
#pragma unroll
    for (int o = 16; o; o >>= 1){
        px2 += __shfl_xor_sync(0xffffffffu, px2, o);
        py2 += __shfl_xor_sync(0xffffffffu, py2, o);
        pxy += __shfl_xor_sync(0xffffffffu, pxy, o);
    }
    float fA = 1.f - 2.f * pxy + py2;
    float fB = 1.f - px2;
    float invden = f_rcp(fmaxf(1.f - 2.f * pxy + px2 * py2, EPSF));

    float4 sub[4];
    float psn2 = 0.f;
#pragma unroll
    for (int i = 0; i < 4; i++){
        sub[i].x = (fB * xc[i].x - fA * xp[i].x) * invden;
        sub[i].y = (fB * xc[i].y - fA * xp[i].y) * invden;
        sub[i].z = (fB * xc[i].z - fA * xp[i].z) * invden;
        sub[i].w = (fB * xc[i].w - fA * xp[i].w) * invden;
        psn2 += sub[i].x*sub[i].x + sub[i].y*sub[i].y + sub[i].z*sub[i].z + sub[i].w*sub[i].w;
    }
#pragma unroll
    for (int o = 16; o; o >>= 1) psn2 += __shfl_xor_sync(0xffffffffu, psn2, o);
    float sn2 = psn2;
    float sn  = f_sqrt(fmaxf(sn2, EPSF));
    float c   = fmaxf(fB, EPSF) * atanh_f(fminf(sn, CLIPA)) * f_rcp(sn);
    float un  = f_sqrt(fmaxf(c * c * sn2, EPSF));
    float s   = tanh_f(un) * c * f_rcp(un);

    uint2* ub = (uint2*)(g_ub + (size_t)row * KTOT);
#pragma unroll
    for (int i = 0; i < 4; i++){
        float u0 = s*sub[i].x, u1 = s*sub[i].y, u2 = s*sub[i].z, u3 = s*sub[i].w;
        __nv_bfloat16 h0=__float2bfloat16(u0), h1=__float2bfloat16(u1),
                      h2=__float2bfloat16(u2), h3=__float2bfloat16(u3);
        __nv_bfloat16 l0=__float2bfloat16(u0-__bfloat162float(h0)),
                      l1=__float2bfloat16(u1-__bfloat162float(h1)),
                      l2=__float2bfloat16(u2-__bfloat162float(h2)),
                      l3=__float2bfloat16(u3-__bfloat162float(h3));
        uint2 hv, lv;
        hv.x = (uint32_t)__bfloat16_as_ushort(h0) | ((uint32_t)__bfloat16_as_ushort(h1) << 16);
        hv.y = (uint32_t)__bfloat16_as_ushort(h2) | ((uint32_t)__bfloat16_as_ushort(h3) << 16);
        lv.x = (uint32_t)__bfloat16_as_ushort(l0) | ((uint32_t)__bfloat16_as_ushort(l1) << 16);
        lv.y = (uint32_t)__bfloat16_as_ushort(l2) | ((uint32_t)__bfloat16_as_ushort(l3) << 16);
        int q = i * 32 + l;
        ub[q]       = hv;   // Uh  @ [0,512)
        ub[128 + q] = lv;   // Ul  @ [512,1024)
        ub[256 + q] = hv;   // Uh  @ [1024,1536)
    }
    if (l == 0){
        g_cu2[row] = s * s * sn2;
        g_x2c[row] = py2;
    }
}

// ------------------------------------------------------------------
// Kernel 3: bf16 HMMA GEMM  g_inner = A'(65536x1536) @ B'(512x1536)^T
// CTA 128x128, BK=64, 3-stage cp.async, 8 warps of 64x32.
// ------------------------------------------------------------------
#define BM 128
#define BN 128
#define BK 64
#define STAGE_BYTES (BM*BK*2 + BN*BK*2)   /* 32768 */
#define NKT (KTOT / BK)                   /* 24 */

__global__ void __launch_bounds__(256) gemm_mma(){
    extern __shared__ __align__(128) char sm[];
    uint32_t sb = s2u(sm);
    int tid = threadIdx.x;
    int wid = tid >> 5, lane = tid & 31;
    int m0 = blockIdx.y * BM;
    int n0 = blockIdx.x * BN;
    int wm = wid & 1;        // 2 warps over M
    int wn = wid >> 1;       // 4 warps over N

    const char* gA = (const char*)g_ub;
    const char* gB = (const char*)g_zb;

    float acc[4][4][4];
#pragma unroll
    for (int i=0;i<4;i++)
#pragma unroll
        for (int j=0;j<4;j++)
#pragma unroll
            for (int k=0;k<4;k++) acc[i][j][k] = 0.f;

    // per-thread load coords (8 x 16B per stage: 4 for A, 4 for B)
    int lr = tid >> 3;              // 0..31  (row step 32)
    int lc = tid & 7;               // chunk 0..7 (16B each, 128B row)

#define LOAD_STAGE(s, kt) do {                                                 \
        uint32_t base_ = sb + (s) * STAGE_BYTES;                               \
        size_t k0_ = (size_t)(kt) * BK;                                        \
        _Pragma("unroll")                                                      \
        for (int it = 0; it < 4; it++){                                        \
            int r_ = it * 32 + lr;                                             \
            uint32_t so_ = base_ + r_ * 128 + ((lc ^ (r_ & 7)) << 4);          \
            cp16(so_, gA + ((size_t)(m0 + r_) * KTOT + k0_) * 2 + (lc << 4));  \
        }                                                                      \
        _Pragma("unroll")                                                      \
        for (int it = 0; it < 4; it++){                                        \
            int r_ = it * 32 + lr;                                             \
            uint32_t so_ = base_ + 16384 + r_ * 128 + ((lc ^ (r_ & 7)) << 4);  \
            cp16(so_, gB + ((size_t)(n0 + r_) * KTOT + k0_) * 2 + (lc << 4));  \
        }                                                                      \
    } while (0)

    LOAD_STAGE(0, 0); cp_commit();
    LOAD_STAGE(1, 1); cp_commit();

    // ldmatrix source addresses (row within tile = lane&15, k-half = lane>>4)
    int lrow = lane & 15;
    int khalf = lane >> 4;

#pragma unroll 1
    for (int kt = 0; kt < NKT; kt++){
        cp_wait<1>();
        __syncthreads();
        int st = kt % 3;
        uint32_t aBase = sb + st * STAGE_BYTES;
        uint32_t bBase = aBase + 16384;
#pragma unroll
        for (int ks = 0; ks < 4; ks++){
            int c16 = ks * 2 + khalf;
            uint32_t a[4][4], bb[2][4];
#pragma unroll
            for (int i = 0; i < 4; i++){
                int row = wm * 64 + i * 16 + lrow;
                ldsm4(a[i], aBase + row * 128 + ((c16 ^ (row & 7)) << 4));
            }
#pragma unroll
            for (int j = 0; j < 2; j++){
                int row = wn * 32 + j * 16 + lrow;
                ldsm4(bb[j], bBase + row * 128 + ((c16 ^ (row & 7)) << 4));
            }
#pragma unroll
            for (int mi = 0; mi < 4; mi++)
#pragma unroll
                for (int ni = 0; ni < 4; ni++)
                    mma16816(acc[mi][ni], a[mi], bb[ni >> 1][ni & 1], bb[ni >> 1][(ni & 1) + 2]);
        }
        if (kt + 2 < NKT) LOAD_STAGE((kt + 2) % 3, kt + 2);
        cp_commit();
        __syncthreads();
    }

    // epilogue: direct float2 stores
    int erow = lane >> 2;
    int ecol = (lane & 3) * 2;
#pragma unroll
    for (int mi = 0; mi < 4; mi++){
#pragma unroll
        for (int ni = 0; ni < 4; ni++){
            int r = m0 + wm * 64 + mi * 16 + erow;
            int c = n0 + wn * 32 + ni * 8 + ecol;
            float* p = g_inner + (size_t)r * DIM + c;
            *(float2*)p             = make_float2(acc[mi][ni][0], acc[mi][ni][1]);
            *(float2*)(p + 8 * DIM) = make_float2(acc[mi][ni][2], acc[mi][ni][3]);
        }
    }
}

// ------------------------------------------------------------------
// Kernel 4: warp-per-row epilogue (fast transcendentals)
// ------------------------------------------------------------------
__global__ void __launch_bounds__(256) finish_rows(const float* __restrict__ xc_g,
                                                   const float* __restrict__ alpha_p,
                                                   const float* __restrict__ step_p,
                                                   float* __restrict__ out){
    int row = blockIdx.x * 8 + (threadIdx.x >> 5);
    int l   = threadIdx.x & 31;
    const float4* in4 = (const float4*)(g_inner + (size_t)row * DIM);
    const float4* xc4 = (const float4*)(xc_g + (size_t)row * DIM);
    const float4* c14 = (const float4*)g_c1;
    const float4* c24 = (const float4*)g_c2;
    const float4* s24 = (const float4*)g_s2;

    float cu2 = g_cu2[row], x2 = g_x2c[row];
    float invdn = f_rcp(fmaxf(1.f - cu2, EPSF));
    float op = 1.f + cu2;

    float w[16], xcv[16];
    float pw2 = 0.f, pxw = 0.f;
#pragma unroll
    for (int i = 0; i < 4; i++){
        int c4 = i * 32 + l;
        float4 iv = in4[c4], xv = xc4[c4], a = c14[c4], b = c24[c4], sv = s24[c4];
        float t0 = (iv.x * a.x - op * b.x) * invdn;
        float t1 = (iv.y * a.y - op * b.y) * invdn;
        float t2 = (iv.z * a.z - op * b.z) * invdn;
        float t3 = (iv.w * a.w - op * b.w) * invdn;
        float w0 = sinh_asinh(t0, sv.x), w1 = sinh_asinh(t1, sv.y);
        float w2 = sinh_asinh(t2, sv.z), w3 = sinh_asinh(t3, sv.w);
        w[i*4+0]=w0; w[i*4+1]=w1; w[i*4+2]=w2; w[i*4+3]=w3;
        xcv[i*4+0]=xv.x; xcv[i*4+1]=xv.y; xcv[i*4+2]=xv.z; xcv[i*4+3]=xv.w;
        pw2 = fmaf(w0,w0, fmaf(w1,w1, fmaf(w2,w2, fmaf(w3,w3, pw2))));
        pxw = fmaf(xv.x,w0, fmaf(xv.y,w1, fmaf(xv.z,w2, fmaf(xv.w,w3, pxw))));
    }
#pragma unroll
    for (int o = 16; o; o >>= 1){
        pw2 += __shfl_xor_sync(0xffffffffu, pw2, o);
        pxw += __shfl_xor_sync(0xffffffffu, pxw, o);
    }
    float w2s = pw2, xw = pxw;

    float gg  = 1.f + f_sqrt(1.f + w2s);
    float rg  = f_rcp(gg);
    float yn  = f_sqrt(fmaxf(w2s * rg * rg, EPSF));
    float kv  = atanh_f(fminf(yn, CLIPA)) * f_rcp(yn);
    float step = sigmoid_f(step_p[0]);
    float m0s = step * kv * rg;
    float un  = f_sqrt(fmaxf(m0s * m0s * w2s, EPSF));
    float lam = 2.f * f_rcp(fmaxf(1.f - x2, EPSF));
    float mt  = tanh_f(0.5f * lam * un) * m0s * f_rcp(un);

    float t2s = mt * mt * w2s;
    float xt  = mt * xw;
    float pp  = 1.f + 2.f * xt + t2s;
    float qq  = 1.f - x2;
    float id2 = f_rcp(fmaxf(1.f + 2.f * xt + x2 * t2s, EPSF));
    float a1  = pp * id2, b1 = qq * mt * id2;

    float nxu2 = a1*a1*x2 + 2.f*a1*b1*xw + b1*b1*w2s;
    float nxu  = f_sqrt(fmaxf(nxu2, EPSF));
    float fxu  = (nxu > MAXN) ? MAXN * f_rcp(nxu) : 1.f;
    a1 *= fxu; b1 *= fxu;
    float nxup = fminf(nxu, MAXN);

    float nxc  = f_sqrt(fmaxf(x2, EPSF));
    float fxc  = (nxc > MAXN) ? MAXN * f_rcp(nxc) : 1.f;
    float nxcp = fminf(nxc, MAXN);

    float aa  = sigmoid_f(alpha_p[0]);
    float th1 = tanh_f(aa * atanh_f(fminf(nxcp, CLIPA)));
    float A1  = th1 * f_rcp(nxcp) * fxc;
    float th2 = tanh_f((1.f - aa) * atanh_f(fminf(nxup, CLIPA)));
    float r2  = th2 * f_rcp(nxup);
    float A2  = r2 * a1, B2 = r2 * b1;

    float x2m = th1 * th1, y2m = th2 * th2;
    float xym = A1 * (A2 * x2 + B2 * xw);
    float P   = 1.f + 2.f * xym + y2m;
    float Q   = 1.f - x2m;
    float id3 = f_rcp(fmaxf(1.f + 2.f * xym + x2m * y2m, EPSF));
    float CA  = (P * A1 + Q * A2) * id3;
    float CB  = (Q * B2) * id3;

    float nn2 = CA*CA*x2 + 2.f*CA*CB*xw + CB*CB*w2s;
    float nn  = f_sqrt(fmaxf(nn2, EPSF));
    float fo  = (nn > MAXN) ? MAXN * f_rcp(nn) : 1.f;
    CA *= fo; CB *= fo;

    float4* o1p = (float4*)(out + (size_t)row * DIM);
    float4* o2p = (float4*)(out + (size_t)BD + (size_t)row * DIM);
#pragma unroll
    for (int i = 0; i < 4; i++){
        int c4 = i * 32 + l;
        float4 o1, o2;
        o1.x = CA*xcv[i*4+0] + CB*w[i*4+0];  o2.x = fxc*xcv[i*4+0];
        o1.y = CA*xcv[i*4+1] + CB*w[i*4+1];  o2.y = fxc*xcv[i*4+1];
        o1.z = CA*xcv[i*4+2] + CB*w[i*4+2];  o2.z = fxc*xcv[i*4+2];
        o1.w = CA*xcv[i*4+3] + CB*w[i*4+3];  o2.w = fxc*xcv[i*4+3];
        o1p[c4] = o1;
        o2p[c4] = o2;
    }
}

// ------------------------------------------------------------------
extern "C" void kernel_launch(void* const* d_in, const int* in_sizes, int n_in,
                              void* d_out, int out_size) {
    const float* xc    = (const float*)d_in[0];
    const float* xp    = (const float*)d_in[1];
    const float* z     = (const float*)d_in[2];
    const float* bias  = (const float*)d_in[3];
    const float* alpha = (const float*)d_in[4];
    const float* stepz = (const float*)d_in[5];
    float* out = (float*)d_out;

    static int smem_set = 0;
    if (!smem_set){
        cudaFuncSetAttribute(gemm_mma, cudaFuncAttributeMaxDynamicSharedMemorySize,
                             3 * STAGE_BYTES);
        smem_set = 1;
    }

    prep_cols<<<DIM, 128>>>(z, bias);
    prep_rows<<<B_ROWS / 8, 256>>>(xc, xp);
    gemm_mma<<<dim3(DIM / BN, B_ROWS / BM), 256, 3 * STAGE_BYTES>>>();
    finish_rows<<<B_ROWS / 8, 256>>>(xc, alpha, stepz, out);
}

// round 4
// speedup vs baseline: 3.5561x; 1.3098x over previous
#include <cuda_runtime.h>
#include <cuda_bf16.h>
#include <stdint.h>
#include <math.h>

#define B_ROWS 65536
#define DIM    512
#define KTOT   1024            /* [Uh | Ul] x [Zh | Zl] : all 4 split terms */
#define BD     (B_ROWS * DIM)
#define EPSF   1e-15f
#define MAXN   0.996f
#define CLIPA  (1.0f - 1e-7f)

// ------------------------------------------------------------------
// Static scratch
// ------------------------------------------------------------------
__device__ __align__(16) __nv_bfloat16 g_ub[(size_t)B_ROWS * KTOT]; // A' [B][1024]
__device__ __align__(16) __nv_bfloat16 g_zb[DIM * KTOT];            // B' [out j][1024]
__device__ __align__(16) float g_inner[BD];
__device__ float g_cu2[B_ROWS];
__device__ float g_x2c[B_ROWS];
__device__ __align__(16) float g_c1[DIM];   // 2*cosh(2b)/zn
__device__ __align__(16) float g_c2[DIM];   // sinh(2b)
__device__ __align__(16) float g_s2[DIM];   // 2*zn

// ------------------------------------------------------------------
// Fast math (MUFU-based)
// ------------------------------------------------------------------
__device__ __forceinline__ float f_rcp(float x){ float y; asm("rcp.approx.f32 %0,%1;" : "=f"(y) : "f"(x)); return y; }
__device__ __forceinline__ float f_lg2(float x){ float y; asm("lg2.approx.f32 %0,%1;" : "=f"(y) : "f"(x)); return y; }
__device__ __forceinline__ float f_ex2(float x){ float y; asm("ex2.approx.f32 %0,%1;" : "=f"(y) : "f"(x)); return y; }
__device__ __forceinline__ float f_sqrt(float x){ float y; asm("sqrt.approx.f32 %0,%1;" : "=f"(y) : "f"(x)); return y; }

__device__ __forceinline__ float atanh_f(float x){
    return 0.34657359028f * f_lg2((1.f + x) * f_rcp(1.f - x));
}
__device__ __forceinline__ float tanh_f(float x){
    return 1.f - 2.f * f_rcp(f_ex2(x * 2.88539008178f) + 1.f);
}
__device__ __forceinline__ float sigmoid_f(float x){
    return f_rcp(1.f + f_ex2(-1.44269504089f * x));
}
__device__ __forceinline__ float sinh_asinh(float t, float s){
    float a = fabsf(t);
    float q = a + f_sqrt(fmaf(a, a, 1.f));
    float p = f_ex2(s * f_lg2(q));
    return copysignf(0.5f * (p - f_rcp(p)), t);
}

// ------------------------------------------------------------------
// Portable tensor-core primitives (sm_80 feature set)
// ------------------------------------------------------------------
__device__ __forceinline__ uint32_t s2u(const void* p){ return (uint32_t)__cvta_generic_to_shared(p); }

__device__ __forceinline__ void cp16(uint32_t dst, const void* src){
    asm volatile("cp.async.cg.shared.global [%0], [%1], 16;" :: "r"(dst), "l"(src));
}
__device__ __forceinline__ void cp_commit(){ asm volatile("cp.async.commit_group;" ::: "memory"); }
template<int N> __device__ __forceinline__ void cp_wait(){ asm volatile("cp.async.wait_group %0;" :: "n"(N) : "memory"); }

__device__ __forceinline__ void ldsm4(uint32_t* r, uint32_t addr){
    asm volatile("ldmatrix.sync.aligned.m8n8.x4.shared.b16 {%0,%1,%2,%3}, [%4];"
        : "=r"(r[0]),"=r"(r[1]),"=r"(r[2]),"=r"(r[3]) : "r"(addr));
}
__device__ __forceinline__ void mma16816(float* c, const uint32_t* a, uint32_t b0, uint32_t b1){
    asm volatile("mma.sync.aligned.m16n8k16.row.col.f32.bf16.bf16.f32 "
        "{%0,%1,%2,%3}, {%4,%5,%6,%7}, {%8,%9}, {%0,%1,%2,%3};"
        : "+f"(c[0]),"+f"(c[1]),"+f"(c[2]),"+f"(c[3])
        : "r"(a[0]),"r"(a[1]),"r"(a[2]),"r"(a[3]), "r"(b0),"r"(b1));
}

// ------------------------------------------------------------------
// Kernel 1: z stats + transposed bf16 split of z into B' = [Zh|Zl]
// ------------------------------------------------------------------
__global__ void prep_cols(const float* __restrict__ z, const float* __restrict__ bias){
    __shared__ float sb[4];
    int j = blockIdx.x, t = threadIdx.x;
    float s = 0.f;
    for (int i = t; i < DIM; i += 128){
        float v = z[i * DIM + j];
        s += v * v;
        __nv_bfloat16 h = __float2bfloat16(v);
        __nv_bfloat16 lo = __float2bfloat16(v - __bfloat162float(h));
        g_zb[j * KTOT + i]       = h;
        g_zb[j * KTOT + DIM + i] = lo;
    }
#pragma unroll
    for (int o = 16; o; o >>= 1) s += __shfl_down_sync(0xffffffffu, s, o);
    if ((t & 31) == 0) sb[t >> 5] = s;
    __syncthreads();
    if (t == 0){
        float tot = sb[0] + sb[1] + sb[2] + sb[3];
        float zn = sqrtf(fmaxf(tot, EPSF));
        float tb = 2.f * bias[j];
        g_c1[j] = 2.f * coshf(tb) / zn;
        g_c2[j] = sinhf(tb);
        g_s2[j] = 2.f * zn;
    }
}

// ------------------------------------------------------------------
// Kernel 2: warp-per-row: u = expmap0(logmap(xp,xc)) -> A' = [Uh|Ul]
// ------------------------------------------------------------------
__global__ void __launch_bounds__(256) prep_rows(const float* __restrict__ xc_g,
                                                 const float* __restrict__ xp_g){
    int row = blockIdx.x * 8 + (threadIdx.x >> 5);
    int l   = threadIdx.x & 31;
    const float4* xc4 = (const float4*)(xc_g + (size_t)row * DIM);
    const float4* xp4 = (const float4*)(xp_g + (size_t)row * DIM);

    float4 xc[4], xp[4];
    float px2 = 0.f, py2 = 0.f, pxy = 0.f;
#pragma unroll
    for (int i = 0; i < 4; i++){
        xc[i] = xc4[i * 32 + l];
        xp[i] = xp4[i * 32 + l];
        px2 += xp[i].x*xp[i].x + xp[i].y*xp[i].y + xp[i].z*xp[i].z + xp[i].w*xp[i].w;
        py2 += xc[i].x*xc[i].x + xc[i].y*xc[i].y + xc[i].z*xc[i].z + xc[i].w*xc[i].w;
        pxy += xp[i].x*xc[i].x + xp[i].y*xc[i].y + xp[i].z*xc[i].z + xp[i].w*xc[i].w;
    }
#pragma unroll
    for (int o = 16; o; o >>= 1){
        px2 += __shfl_xor_sync(0xffffffffu, px2, o);
        py2 += __shfl_xor_sync(0xffffffffu, py2, o);
        pxy += __shfl_xor_sync(0xffffffffu, pxy, o);
    }
    float fA = 1.f - 2.f * pxy + py2;
    float fB = 1.f - px2;
    float invden = f_rcp(fmaxf(1.f - 2.f * pxy + px2 * py2, EPSF));

    float4 sub[4];
    float psn2 = 0.f;
#pragma unroll
    for (int i = 0; i < 4; i++){
        sub[i].x = (fB * xc[i].x - fA * xp[i].x) * invden;
        sub[i].y = (fB * xc[i].y - fA * xp[i].y) * invden;
        sub[i].z = (fB * xc[i].z - fA * xp[i].z) * invden;
        sub[i].w = (fB * xc[i].w - fA * xp[i].w) * invden;
        psn2 += sub[i].x*sub[i].x + sub[i].y*sub[i].y + sub[i].z*sub[i].z + sub[i].w*sub[i].w;
    }
#pragma unroll
    for (int o = 16; o; o >>= 1) psn2 += __shfl_xor_sync(0xffffffffu, psn2, o);
    float sn2 = psn2;
    float sn  = f_sqrt(fmaxf(sn2, EPSF));
    float c   = fmaxf(fB, EPSF) * atanh_f(fminf(sn, CLIPA)) * f_rcp(sn);
    float un  = f_sqrt(fmaxf(c * c * sn2, EPSF));
    float s   = tanh_f(un) * c * f_rcp(un);

    uint2* ub = (uint2*)(g_ub + (size_t)row * KTOT);
#pragma unroll
    for (int i = 0; i < 4; i++){
        float u0 = s*sub[i].x, u1 = s*sub[i].y, u2 = s*sub[i].z, u3 = s*sub[i].w;
        __nv_bfloat16 h0=__float2bfloat16(u0), h1=__float2bfloat16(u1),
                      h2=__float2bfloat16(u2), h3=__float2bfloat16(u3);
        __nv_bfloat16 l0=__float2bfloat16(u0-__bfloat162float(h0)),
                      l1=__float2bfloat16(u1-__bfloat162float(h1)),
                      l2=__float2bfloat16(u2-__bfloat162float(h2)),
                      l3=__float2bfloat16(u3-__bfloat162float(h3));
        uint2 hv, lv;
        hv.x = (uint32_t)__bfloat16_as_ushort(h0) | ((uint32_t)__bfloat16_as_ushort(h1) << 16);
        hv.y = (uint32_t)__bfloat16_as_ushort(h2) | ((uint32_t)__bfloat16_as_ushort(h3) << 16);
        lv.x = (uint32_t)__bfloat16_as_ushort(l0) | ((uint32_t)__bfloat16_as_ushort(l1) << 16);
        lv.y = (uint32_t)__bfloat16_as_ushort(l2) | ((uint32_t)__bfloat16_as_ushort(l3) << 16);
        int q = i * 32 + l;
        ub[q]       = hv;   // Uh @ [0,512)
        ub[128 + q] = lv;   // Ul @ [512,1024)
    }
    if (l == 0){
        g_cu2[row] = s * s * sn2;
        g_x2c[row] = py2;
    }
}

// ------------------------------------------------------------------
// Kernel 3: bf16 HMMA GEMM  g_inner = A'(65536x1024) @ B'(512x1024)^T
// CTA 128x256, BK=64, 3-stage cp.async, 8 warps of 64x64.
// ------------------------------------------------------------------
#define BM 128
#define BN 256
#define BK 64
#define A_BYTES (BM*BK*2)                  /* 16384 */
#define B_BYTES (BN*BK*2)                  /* 32768 */
#define STAGE_BYTES (A_BYTES + B_BYTES)    /* 49152 */
#define NKT (KTOT / BK)                    /* 16 */

__global__ void __launch_bounds__(256, 1) gemm_mma(){
    extern __shared__ __align__(128) char sm[];
    uint32_t sb = s2u(sm);
    int tid = threadIdx.x;
    int wid = tid >> 5, lane = tid & 31;
    int m0 = blockIdx.y * BM;
    int n0 = blockIdx.x * BN;
    int wm = wid & 1;        // 2 warps over M (64 each)
    int wn = wid >> 1;       // 4 warps over N (64 each)

    const char* gA = (const char*)g_ub;
    const char* gB = (const char*)g_zb;

    float acc[4][8][4];
#pragma unroll
    for (int i=0;i<4;i++)
#pragma unroll
        for (int j=0;j<8;j++)
#pragma unroll
            for (int k=0;k<4;k++) acc[i][j][k] = 0.f;

    int lr = tid >> 3;              // 0..31
    int lc = tid & 7;               // 16B chunk within 128B row

#define LOAD_STAGE(s, kt) do {                                                 \
        uint32_t base_ = sb + (s) * STAGE_BYTES;                               \
        size_t k0_ = (size_t)(kt) * BK;                                        \
        _Pragma("unroll")                                                      \
        for (int it = 0; it < 4; it++){                                        \
            int r_ = it * 32 + lr;                                             \
            uint32_t so_ = base_ + r_ * 128 + ((lc ^ (r_ & 7)) << 4);          \
            cp16(so_, gA + ((size_t)(m0 + r_) * KTOT + k0_) * 2 + (lc << 4));  \
        }                                                                      \
        _Pragma("unroll")                                                      \
        for (int it = 0; it < 8; it++){                                        \
            int r_ = it * 32 + lr;                                             \
            uint32_t so_ = base_ + A_BYTES + r_ * 128 + ((lc ^ (r_ & 7)) << 4);\
            cp16(so_, gB + ((size_t)(n0 + r_) * KTOT + k0_) * 2 + (lc << 4));  \
        }                                                                      \
    } while (0)

    LOAD_STAGE(0, 0); cp_commit();
    LOAD_STAGE(1, 1); cp_commit();

    int lrow = lane & 15;
    int khalf = lane >> 4;

#pragma unroll 1
    for (int kt = 0; kt < NKT; kt++){
        cp_wait<1>();
        __syncthreads();
        int st = kt % 3;
        uint32_t aBase = sb + st * STAGE_BYTES;
        uint32_t bBase = aBase + A_BYTES;
#pragma unroll
        for (int ks = 0; ks < 4; ks++){
            int c16 = ks * 2 + khalf;
            uint32_t a[4][4], bb[4][4];
#pragma unroll
            for (int i = 0; i < 4; i++){
                int row = wm * 64 + i * 16 + lrow;
                ldsm4(a[i], aBase + row * 128 + ((c16 ^ (row & 7)) << 4));
            }
#pragma unroll
            for (int j = 0; j < 4; j++){
                int row = wn * 64 + j * 16 + lrow;
                ldsm4(bb[j], bBase + row * 128 + ((c16 ^ (row & 7)) << 4));
            }
#pragma unroll
            for (int mi = 0; mi < 4; mi++)
#pragma unroll
                for (int ni = 0; ni < 8; ni++)
                    mma16816(acc[mi][ni], a[mi], bb[ni >> 1][ni & 1], bb[ni >> 1][(ni & 1) + 2]);
        }
        if (kt + 2 < NKT){ LOAD_STAGE((kt + 2) % 3, kt + 2); }
        cp_commit();
    }

    // epilogue: direct float2 stores
    int erow = lane >> 2;
    int ecol = (lane & 3) * 2;
#pragma unroll
    for (int mi = 0; mi < 4; mi++){
#pragma unroll
        for (int ni = 0; ni < 8; ni++){
            int r = m0 + wm * 64 + mi * 16 + erow;
            int c = n0 + wn * 64 + ni * 8 + ecol;
            float* p = g_inner + (size_t)r * DIM + c;
            *(float2*)p             = make_float2(acc[mi][ni][0], acc[mi][ni][1]);
            *(float2*)(p + 8 * DIM) = make_float2(acc[mi][ni][2], acc[mi][ni][3]);
        }
    }
}

// ------------------------------------------------------------------
// Kernel 4: warp-per-row epilogue (fast transcendentals)
// ------------------------------------------------------------------
__global__ void __launch_bounds__(256) finish_rows(const float* __restrict__ xc_g,
                                                   const float* __restrict__ alpha_p,
                                                   const float* __restrict__ step_p,
                                                   float* __restrict__ out){
    int row = blockIdx.x * 8 + (threadIdx.x >> 5);
    int l   = threadIdx.x & 31;
    const float4* in4 = (const float4*)(g_inner + (size_t)row * DIM);
    const float4* xc4 = (const float4*)(xc_g + (size_t)row * DIM);
    const float4* c14 = (const float4*)g_c1;
    const float4* c24 = (const float4*)g_c2;
    const float4* s24 = (const float4*)g_s2;

    float cu2 = g_cu2[row], x2 = g_x2c[row];
    float invdn = f_rcp(fmaxf(1.f - cu2, EPSF));
    float op = 1.f + cu2;

    float w[16], xcv[16];
    float pw2 = 0.f, pxw = 0.f;
#pragma unroll
    for (int i = 0; i < 4; i++){
        int c4 = i * 32 + l;
        float4 iv = in4[c4], xv = xc4[c4], a = c14[c4], b = c24[c4], sv = s24[c4];
        float t0 = (iv.x * a.x - op * b.x) * invdn;
        float t1 = (iv.y * a.y - op * b.y) * invdn;
        float t2 = (iv.z * a.z - op * b.z) * invdn;
        float t3 = (iv.w * a.w - op * b.w) * invdn;
        float w0 = sinh_asinh(t0, sv.x), w1 = sinh_asinh(t1, sv.y);
        float w2 = sinh_asinh(t2, sv.z), w3 = sinh_asinh(t3, sv.w);
        w[i*4+0]=w0; w[i*4+1]=w1; w[i*4+2]=w2; w[i*4+3]=w3;
        xcv[i*4+0]=xv.x; xcv[i*4+1]=xv.y; xcv[i*4+2]=xv.z; xcv[i*4+3]=xv.w;
        pw2 = fmaf(w0,w0, fmaf(w1,w1, fmaf(w2,w2, fmaf(w3,w3, pw2))));
        pxw = fmaf(xv.x,w0, fmaf(xv.y,w1, fmaf(xv.z,w2, fmaf(xv.w,w3, pxw))));
    }
#pragma unroll
    for (int o = 16; o; o >>= 1){
        pw2 += __shfl_xor_sync(0xffffffffu, pw2, o);
        pxw += __shfl_xor_sync(0xffffffffu, pxw, o);
    }
    float w2s = pw2, xw = pxw;

    float gg  = 1.f + f_sqrt(1.f + w2s);
    float rg  = f_rcp(gg);
    float yn  = f_sqrt(fmaxf(w2s * rg * rg, EPSF));
    float kv  = atanh_f(fminf(yn, CLIPA)) * f_rcp(yn);
    float step = sigmoid_f(step_p[0]);
    float m0s = step * kv * rg;
    float un  = f_sqrt(fmaxf(m0s * m0s * w2s, EPSF));
    float lam = 2.f * f_rcp(fmaxf(1.f - x2, EPSF));
    float mt  = tanh_f(0.5f * lam * un) * m0s * f_rcp(un);

    float t2s = mt * mt * w2s;
    float xt  = mt * xw;
    float pp  = 1.f + 2.f * xt + t2s;
    float qq  = 1.f - x2;
    float id2 = f_rcp(fmaxf(1.f + 2.f * xt + x2 * t2s, EPSF));
    float a1  = pp * id2, b1 = qq * mt * id2;

    float nxu2 = a1*a1*x2 + 2.f*a1*b1*xw + b1*b1*w2s;
    float nxu  = f_sqrt(fmaxf(nxu2, EPSF));
    float fxu  = (nxu > MAXN) ? MAXN * f_rcp(nxu) : 1.f;
    a1 *= fxu; b1 *= fxu;
    float nxup = fminf(nxu, MAXN);

    float nxc  = f_sqrt(fmaxf(x2, EPSF));
    float fxc  = (nxc > MAXN) ? MAXN * f_rcp(nxc) : 1.f;
    float nxcp = fminf(nxc, MAXN);

    float aa  = sigmoid_f(alpha_p[0]);
    float th1 = tanh_f(aa * atanh_f(fminf(nxcp, CLIPA)));
    float A1  = th1 * f_rcp(nxcp) * fxc;
    float th2 = tanh_f((1.f - aa) * atanh_f(fminf(nxup, CLIPA)));
    float r2  = th2 * f_rcp(nxup);
    float A2  = r2 * a1, B2 = r2 * b1;

    float x2m = th1 * th1, y2m = th2 * th2;
    float xym = A1 * (A2 * x2 + B2 * xw);
    float P   = 1.f + 2.f * xym + y2m;
    float Q   = 1.f - x2m;
    float id3 = f_rcp(fmaxf(1.f + 2.f * xym + x2m * y2m, EPSF));
    float CA  = (P * A1 + Q * A2) * id3;
    float CB  = (Q * B2) * id3;

    float nn2 = CA*CA*x2 + 2.f*CA*CB*xw + CB*CB*w2s;
    float nn  = f_sqrt(fmaxf(nn2, EPSF));
    float fo  = (nn > MAXN) ? MAXN * f_rcp(nn) : 1.f;
    CA *= fo; CB *= fo;

    float4* o1p = (float4*)(out + (size_t)row * DIM);
    float4* o2p = (float4*)(out + (size_t)BD + (size_t)row * DIM);
#pragma unroll
    for (int i = 0; i < 4; i++){
        int c4 = i * 32 + l;
        float4 o1, o2;
        o1.x = CA*xcv[i*4+0] + CB*w[i*4+0];  o2.x = fxc*xcv[i*4+0];
        o1.y = CA*xcv[i*4+1] + CB*w[i*4+1];  o2.y = fxc*xcv[i*4+1];
        o1.z = CA*xcv[i*4+2] + CB*w[i*4+2];  o2.z = fxc*xcv[i*4+2];
        o1.w = CA*xcv[i*4+3] + CB*w[i*4+3];  o2.w = fxc*xcv[i*4+3];
        o1p[c4] = o1;
        o2p[c4] = o2;
    }
}

// ------------------------------------------------------------------
extern "C" void kernel_launch(void* const* d_in, const int* in_sizes, int n_in,
                              void* d_out, int out_size) {
    const float* xc    = (const float*)d_in[0];
    const float* xp    = (const float*)d_in[1];
    const float* z     = (const float*)d_in[2];
    const float* bias  = (const float*)d_in[3];
    const float* alpha = (const float*)d_in[4];
    const float* stepz = (const float*)d_in[5];
    float* out = (float*)d_out;

    static int smem_set = 0;
    if (!smem_set){
        cudaFuncSetAttribute(gemm_mma, cudaFuncAttributeMaxDynamicSharedMemorySize,
                             3 * STAGE_BYTES);
        smem_set = 1;
    }

    prep_cols<<<DIM, 128>>>(z, bias);
    prep_rows<<<B_ROWS / 8, 256>>>(xc, xp);
    gemm_mma<<<dim3(DIM / BN, B_ROWS / BM), 256, 3 * STAGE_BYTES>>>();
    finish_rows<<<B_ROWS / 8, 256>>>(xc, alpha, stepz, out);
}